// round 8
// baseline (speedup 1.0000x reference)
#include <cuda_runtime.h>
#include <cstdint>

// depthconv1d: B=8, L=16384, C=512, K=31, SAME padding, fp32 NWC.
// out[b,w,c] = sum_k x[b, w+k-15, c] * ker[k*C + c] + bias[c]
//
// R8: R4's winning one-shot structure, scaled for inter-CTA phase diversity:
// 256-thread blocks, 31KB smem tile (32 w x 128 ch, NR=62 staged rows),
// weights via LDG (L1-resident, no smem), <=64 regs -> 4 CTAs x 8 warps =
// 32 warps/SM (2x R4) of independent one-shot CTAs at finer granularity.
// Lesson from R6: independent CTAs beat intra-CTA pipelining for keeping
// DRAM request queues full.

#define B_ 8
#define L_ 16384
#define C_ 512
#define K_ 31
#define HALF_ 15
#define T_ 8                    // outputs per thread
#define CB_ 128                 // channels per block
#define WB_ 32                  // output rows per block (4 grps x T)
#define NR_ (WB_ + K_ - 1)      // 62 staged input rows
#define ROWB_ (CB_ * 4)         // 512 B per staged row
#define XW_ 10                  // register x-ring slots (8 live + 2 prefetch)
#define NP_ (T_ + K_ - 1)       // 38 rows read per thread

using u64 = unsigned long long;

__device__ __forceinline__ u64 fma2(u64 a, u64 b, u64 c) {
    u64 d;
    asm("fma.rn.f32x2 %0, %1, %2, %3;" : "=l"(d) : "l"(a), "l"(b), "l"(c));
    return d;
}
__device__ __forceinline__ u64 add2(u64 a, u64 b) {
    u64 d;
    asm("add.rn.f32x2 %0, %1, %2;" : "=l"(d) : "l"(a), "l"(b));
    return d;
}
__device__ __forceinline__ void cp_async16(uint32_t sa, const void* g) {
    asm volatile("cp.async.cg.shared.global [%0], [%1], 16;"
                 :: "r"(sa), "l"(g) : "memory");
}
__device__ __forceinline__ void cp_async_wait_all() {
    asm volatile("cp.async.commit_group;\n\tcp.async.wait_group 0;" ::: "memory");
}

template <bool EDGE>
__device__ __forceinline__ void run_body(
    const float* __restrict__ x, const float* __restrict__ w,
    const float* __restrict__ bias, float* __restrict__ out, char* xs)
{
    const int tid = threadIdx.x;
    const int w0  = blockIdx.x * WB_;
    const int cb0 = blockIdx.y * CB_;
    const int b   = blockIdx.z;

    // ---- Stage x: NR_=62 rows x 512B = 1984 16B chunks over 256 threads ----
    {
        const char* gx = reinterpret_cast<const char*>(x)
                       + ((long long)b * L_ * C_ + cb0) * 4ll;
        uint32_t sa0 = (uint32_t)__cvta_generic_to_shared(xs);
#pragma unroll
        for (int j = 0; j < 8; j++) {
            int chunk = j * 256 + tid;
            if (chunk < NR_ * 32) {
                int r = chunk >> 5, lane = chunk & 31;
                int wg = w0 - HALF_ + r;
                if (!EDGE || ((unsigned)wg < (unsigned)L_)) {
                    cp_async16(sa0 + r * ROWB_ + lane * 16,
                               gx + (long long)wg * (C_ * 4) + lane * 16);
                } else {
                    *reinterpret_cast<uint4*>(xs + r * ROWB_ + lane * 16)
                        = make_uint4(0u, 0u, 0u, 0u);
                }
            }
        }
    }
    cp_async_wait_all();
    __syncthreads();

    // ---- Compute: thread = channel pair x T_=8 outputs, k-outer, x-ring ----
    const int pair = tid & 63;              // channels cb0 + 2*pair
    const int grp  = tid >> 6;              // w-subgroup 0..3
    const char* xsp = xs + (grp * T_) * ROWB_ + pair * 8;
    const char* wgp = reinterpret_cast<const char*>(w) + (cb0 + pair * 2) * 4;

    u64 xv[XW_];
#pragma unroll
    for (int p = 0; p < XW_; p++)
        xv[p] = *reinterpret_cast<const u64*>(xsp + p * ROWB_);

    u64 acc[T_];
#pragma unroll
    for (int t = 0; t < T_; t++) acc[t] = 0ull;

    // Weights: direct LDG, L1-resident (62KB total across 4 channel slices),
    // double-buffered one k ahead.
    u64 wcur = *reinterpret_cast<const u64*>(wgp);
#pragma unroll
    for (int k = 0; k < K_; k++) {
        u64 wnext = 0ull;
        if (k + 1 < K_)
            wnext = *reinterpret_cast<const u64*>(wgp + (k + 1) * (C_ * 4));
#pragma unroll
        for (int t = 0; t < T_; t++)
            acc[t] = fma2(xv[(k + t) % XW_], wcur, acc[t]);
        if (k + XW_ < NP_)
            xv[(k + XW_) % XW_] =
                *reinterpret_cast<const u64*>(xsp + (k + XW_) * ROWB_);
        wcur = wnext;
    }

    u64 bv = *reinterpret_cast<const u64*>(bias + cb0 + pair * 2);
    char* ob = reinterpret_cast<char*>(out)
             + ((long long)((long long)b * L_ + w0 + grp * T_) * C_
                + cb0 + pair * 2) * 4ll;
#pragma unroll
    for (int t = 0; t < T_; t++)
        *reinterpret_cast<u64*>(ob + (long long)t * (C_ * 4)) = add2(acc[t], bv);
}

__global__ __launch_bounds__(256, 4)
void depthconv1d_kernel(const float* __restrict__ x,
                        const float* __restrict__ w,
                        const float* __restrict__ bias,
                        float* __restrict__ out)
{
    __shared__ char xs[NR_ * ROWB_];   // 31744 B -> 4 CTAs/SM
    if (blockIdx.x == 0 || blockIdx.x == gridDim.x - 1)
        run_body<true>(x, w, bias, out, xs);
    else
        run_body<false>(x, w, bias, out, xs);
}

extern "C" void kernel_launch(void* const* d_in, const int* in_sizes, int n_in,
                              void* d_out, int out_size)
{
    const float* x    = (const float*)d_in[0];  // [8, 16384, 512]
    const float* ker  = (const float*)d_in[1];  // [31, 512, 1]
    const float* bias = (const float*)d_in[2];  // [512]
    float* out = (float*)d_out;                 // [8, 16384, 512]

    dim3 grid(L_ / WB_, C_ / CB_, B_);   // (512, 4, 8) = 16384 blocks
    dim3 block(256);
    depthconv1d_kernel<<<grid, block>>>(x, ker, bias, out);
}

// round 10
// speedup vs baseline: 1.0859x; 1.0859x over previous
#include <cuda_runtime.h>
#include <cstdint>

// depthconv1d: B=8, L=16384, C=512, K=31, SAME padding, fp32 NWC.
// out[b,w,c] = sum_k x[b, w+k-15, c] * ker[k*C + c] + bias[c]
//
// R9 = R4 (best: 98.8us) with ONE change: grid order swapped so the channel
// slice is the fastest-varying block index. The 4 CTAs covering the four
// 512B quarters of the same 2KB DRAM rows (x reads AND out writes) are now
// launch-adjacent and co-resident -> full-row DRAM activations instead of
// 4x re-activation spread across waves. Theory: achieved HBM BW is limited
// by row-activation overhead from fragmented rows (R1 full-row = 64.8% DRAM
// vs CB=128 kernels at 57-63%).

#define B_ 8
#define L_ 16384
#define C_ 512
#define K_ 31
#define HALF_ 15
#define T_ 16        // outputs per thread
#define WB_ 32       // w positions per block
#define CB_ 128      // channels per block
#define NR_ (WB_ + K_ - 1)   // 62 input rows staged
#define XW_ 18       // register x-ring slots
#define NP_ (T_ + K_ - 1)    // 46 rows read per thread

using u64 = unsigned long long;

__device__ __forceinline__ u64 fma2(u64 a, u64 b, u64 c) {
    u64 d;
    asm("fma.rn.f32x2 %0, %1, %2, %3;" : "=l"(d) : "l"(a), "l"(b), "l"(c));
    return d;
}
__device__ __forceinline__ u64 add2(u64 a, u64 b) {
    u64 d;
    asm("add.rn.f32x2 %0, %1, %2;" : "=l"(d) : "l"(a), "l"(b));
    return d;
}
__device__ __forceinline__ void cp_async16(uint32_t smem_addr, const void* gptr) {
    asm volatile("cp.async.cg.shared.global [%0], [%1], 16;"
                 :: "r"(smem_addr), "l"(gptr) : "memory");
}
__device__ __forceinline__ void cp_async_wait_all() {
    asm volatile("cp.async.commit_group;\n\tcp.async.wait_group 0;" ::: "memory");
}

__global__ __launch_bounds__(128, 4)
void depthconv1d_kernel(const float* __restrict__ x,
                        const float* __restrict__ w,
                        const float* __restrict__ bias,
                        float* __restrict__ out)
{
    __shared__ char xs[NR_ * CB_ * 4];      // 62 rows x 512B = 31744B
    __shared__ char ws[K_ * CB_ * 4];       // 31 rows x 512B = 15872B

    const int tid = threadIdx.x;
    const int cb0 = blockIdx.x * CB_;       // channel slice: FASTEST grid dim
    const int w0  = blockIdx.y * WB_;       // w tile
    const int b   = blockIdx.z;
    const bool edge = (blockIdx.y == 0) | (blockIdx.y == gridDim.y - 1);

    // ---- Stage x tile: rows [w0-15, w0+46] x 512B, 16B chunks ----
    {
        const int lane  = tid & 31;         // 16B chunk within row
        const int rbase = tid >> 5;         // row offset 0..3
        const char* gx = reinterpret_cast<const char*>(x)
                       + ((long long)((long long)b * L_) * C_ + cb0) * 4ll;
        uint32_t s0 = (uint32_t)__cvta_generic_to_shared(xs) + lane * 16;
#pragma unroll
        for (int i = 0; i < 16; i++) {
            int r = i * 4 + rbase;
            if (r < NR_) {
                int wg = w0 - HALF_ + r;
                uint32_t sa = s0 + r * (CB_ * 4);
                if (!edge || ((unsigned)wg < (unsigned)L_)) {
                    cp_async16(sa, gx + (long long)wg * (C_ * 4) + lane * 16);
                } else {
                    *reinterpret_cast<uint4*>(xs + r * (CB_ * 4) + lane * 16)
                        = make_uint4(0u, 0u, 0u, 0u);
                }
            }
        }
    }

    // ---- Stage weights: w[k*C + cb0 .. cb0+127] -> ws[k*512B] ----
    {
        const char* gw = reinterpret_cast<const char*>(w) + cb0 * 4;
        uint32_t sw = (uint32_t)__cvta_generic_to_shared(ws);
#pragma unroll
        for (int j = 0; j < 8; j++) {
            int chunk = j * 128 + tid;
            if (chunk < (K_ * CB_ * 4) / 16) {
                int o  = chunk * 16;
                int k  = o / (CB_ * 4);
                int of = o % (CB_ * 4);
                cp_async16(sw + o, gw + (long long)k * (C_ * 4) + of);
            }
        }
    }

    cp_async_wait_all();
    __syncthreads();

    // ---- Compute: thread = channel pair x 16 outputs, k-outer, x-ring ----
    const int pair = tid & 63;              // f32x2 lane: channels cb0+2*pair
    const int grp  = tid >> 6;              // w-subgroup 0..1
    const char* xsp = xs + grp * T_ * (CB_ * 4) + pair * 8;
    const char* wsp = ws + pair * 8;

    u64 xv[XW_];
#pragma unroll
    for (int p = 0; p < XW_; p++)
        xv[p] = *reinterpret_cast<const u64*>(xsp + p * (CB_ * 4));

    u64 acc[T_];
#pragma unroll
    for (int t = 0; t < T_; t++) acc[t] = 0ull;

    u64 wcur = *reinterpret_cast<const u64*>(wsp);
#pragma unroll
    for (int k = 0; k < K_; k++) {
        u64 wnext = 0ull;
        if (k + 1 < K_)
            wnext = *reinterpret_cast<const u64*>(wsp + (k + 1) * (CB_ * 4));
#pragma unroll
        for (int t = 0; t < T_; t++)
            acc[t] = fma2(xv[(k + t) % XW_], wcur, acc[t]);
        if (k + XW_ < NP_)
            xv[(k + XW_) % XW_] =
                *reinterpret_cast<const u64*>(xsp + (k + XW_) * (CB_ * 4));
        wcur = wnext;
    }

    u64 bv = *reinterpret_cast<const u64*>(bias + cb0 + pair * 2);
    char* ob = reinterpret_cast<char*>(out)
             + ((long long)((long long)b * L_ + w0 + grp * T_) * C_ + cb0 + pair * 2) * 4ll;
#pragma unroll
    for (int t = 0; t < T_; t++) {
        u64 r = add2(acc[t], bv);
        *reinterpret_cast<u64*>(ob + (long long)t * (C_ * 4)) = r;
    }
}

extern "C" void kernel_launch(void* const* d_in, const int* in_sizes, int n_in,
                              void* d_out, int out_size)
{
    const float* x    = (const float*)d_in[0];  // [8, 16384, 512]
    const float* ker  = (const float*)d_in[1];  // [31, 512, 1]
    const float* bias = (const float*)d_in[2];  // [512]
    float* out = (float*)d_out;                 // [8, 16384, 512]

    dim3 grid(C_ / CB_, L_ / WB_, B_);   // (4, 512, 8): channel slice fastest
    dim3 block(128);
    depthconv1d_kernel<<<grid, block>>>(x, ker, bias, out);
}